// round 10
// baseline (speedup 1.0000x reference)
#include <cuda_runtime.h>

// Sobel_16724602651101 — R9
// x: (16, 3, 512, 512) fp32 -> out: [magnitude | angle] each (16,512,512) fp32.
//
// Direct-LDG, no smem/barrier. 16 px/thread: 8 wide x 2 rows. 4 input rows
// per channel serve both output rows (vertical redundancy 3x -> 2x; L1
// wavefronts -33%). Shared horizontal diffs for the 2 middle rows. R8's exact
// power-of-two deferred scaling (gx'=8gx, gy'=8gy, m'=64m), R1's fp grouping,
// sqrt.approx + __fdividef epilogue (rel_err 1.0849e-7 lineage).

#define BATCH 16
#define CH 3
#define HH 512
#define WW 512
#define HW (HH * WW)

#define FULLMASK 0xFFFFFFFFu
#define EPS64 (64.0f * 1e-9f)
#define TINY8 (8.0f * 1e-9f)

__device__ __forceinline__ float fsqrt_approx(float a)
{
    float r;
    asm("sqrt.approx.f32 %0, %1;" : "=f"(r) : "f"(a));
    return r;
}

__global__ __launch_bounds__(256, 2)
void sobel_kernel(const float* __restrict__ x, float* __restrict__ out)
{
    const int lane = threadIdx.x;                          // 0..31
    const int y0   = blockIdx.y * 16 + threadIdx.y * 2;    // first output row
    const int b    = blockIdx.z;
    const int c0   = blockIdx.x * 256 + lane * 8;          // first of 8 cols

    const float* __restrict__ xb = x + (size_t)b * CH * HW;

    // 4 input rows: y0-1, y0, y0+1, y0+2 (clamped)
    const int ro0 = max(y0 - 1, 0) * WW;
    const int ro1 = y0 * WW;
    const int ro2 = (y0 + 1) * WW;                         // y0+1 <= 511 always
    const int ro3 = min(y0 + 2, HH - 1) * WW;
    const int cl  = max(c0 - 1, 0);
    const int cr  = min(c0 + 8, WW - 1);

    float bm[2][8], bgx[2][8], bgy[2][8];

    #pragma unroll
    for (int c = 0; c < CH; c++) {
        const float* __restrict__ xc = xb + c * HW;

        // window: w[i][j] = input row i (of 4), col c0-1+j (j=0..9)
        float w[4][10];
        #pragma unroll
        for (int i = 0; i < 4; i++) {
            const int ro = (i == 0) ? ro0 : (i == 1) ? ro1 : (i == 2) ? ro2 : ro3;
            const float* __restrict__ rp = xc + ro;
            float4 v0 = __ldg((const float4*)(rp + c0));
            float4 v1 = __ldg((const float4*)(rp + c0 + 4));
            float lf = __shfl_up_sync(FULLMASK, v1.w, 1);
            float rt = __shfl_down_sync(FULLMASK, v0.x, 1);
            if (lane == 0)  lf = __ldg(rp + cl);
            if (lane == 31) rt = __ldg(rp + cr);
            w[i][0] = lf;
            w[i][1] = v0.x; w[i][2] = v0.y; w[i][3] = v0.z; w[i][4] = v0.w;
            w[i][5] = v1.x; w[i][6] = v1.y; w[i][7] = v1.z; w[i][8] = v1.w;
            w[i][9] = rt;
        }

        // horizontal diffs, computed once per input row (rows 1,2 shared by
        // both output rows): dr[i][p] = w[i][p+2] - w[i][p]   (R1's gx subs)
        float dr[4][8];
        #pragma unroll
        for (int i = 0; i < 4; i++)
            #pragma unroll
            for (int p = 0; p < 8; p++) dr[i][p] = w[i][p + 2] - w[i][p];

        // vertical diffs per output row: vd[rr][j] = w[rr+2][j] - w[rr][j]
        float vd[2][10];
        #pragma unroll
        for (int j = 0; j < 10; j++) { vd[0][j] = w[2][j] - w[0][j];
                                       vd[1][j] = w[3][j] - w[1][j]; }

        #pragma unroll
        for (int rr = 0; rr < 2; rr++) {
            #pragma unroll
            for (int p = 0; p < 8; p++) {
                // 8x-scaled gx/gy with R1's exact grouping
                float gx = dr[rr][p] + 2.0f * dr[rr + 1][p] + dr[rr + 2][p];
                float gy = vd[rr][p] + 2.0f * vd[rr][p + 1] + vd[rr][p + 2];
                float m  = gx * gx + gy * gy + EPS64;      // 64x-scaled
                if (c == 0) {
                    bm[rr][p] = m; bgx[rr][p] = gx; bgy[rr][p] = gy;
                } else if (m > bm[rr][p]) {   // strict >: first-occurrence argmax
                    bm[rr][p] = m; bgx[rr][p] = gx; bgy[rr][p] = gy;
                }
            }
        }
    }

    const size_t oang = (size_t)BATCH * HW;

    #pragma unroll
    for (int rr = 0; rr < 2; rr++) {
        float mag[8], ang[8];
        #pragma unroll
        for (int p = 0; p < 8; p++) {
            mag[p] = fsqrt_approx(bm[rr][p]) * 0.125f;     // == sqrt(m)/8 bitwise
            float yt = (bgy[rr][p] == 0.f) ? TINY8 : bgy[rr][p];
            ang[p] = fminf(fmaxf(__fdividef(bgx[rr][p], yt), -10.f), 10.f);
        }
        const size_t o = (size_t)b * HW + (size_t)(y0 + rr) * WW + c0;
        float* __restrict__ om = out + o;
        float* __restrict__ oa = out + oang + o;
        *(float4*)(om)     = make_float4(mag[0], mag[1], mag[2], mag[3]);
        *(float4*)(om + 4) = make_float4(mag[4], mag[5], mag[6], mag[7]);
        *(float4*)(oa)     = make_float4(ang[0], ang[1], ang[2], ang[3]);
        *(float4*)(oa + 4) = make_float4(ang[4], ang[5], ang[6], ang[7]);
    }
}

extern "C" void kernel_launch(void* const* d_in, const int* in_sizes, int n_in,
                              void* d_out, int out_size)
{
    const float* x = (const float*)d_in[0];
    float* out = (float*)d_out;

    dim3 block(32, 8, 1);                   // warp = 256-col strip, 2 rows/warp
    dim3 grid(WW / 256, HH / 16, BATCH);    // (2, 32, 16) = 1024 blocks
    sobel_kernel<<<grid, block>>>(x, out);
}